// round 3
// baseline (speedup 1.0000x reference)
#include <cuda_runtime.h>
#include <stdint.h>

#define NN 16384
#define BB 64
#define TS 32768          // hash table slots (2x N, power of 2)
#define RPB 8             // rows per block in heavy kernel

// ---------------- device scratch (static, no allocation) ----------------
__device__ __align__(16) unsigned int g_Kc[NN];    // per-column hash multiplier = f(x[j])
__device__ unsigned long long g_acc[NN];           // per-row neighbor-multiset hash accumulator
__device__ unsigned int       g_deg[NN];           // per-row nonzero count (exact)
__device__ __align__(16) unsigned int g_colAnyW[NN / 4]; // per-column any-nonzero (byte/col)
__device__ unsigned long long g_key[NN];           // final signature key (0 for isolated)
__device__ unsigned long long g_tabKey[TS];        // hash table keys (0 = empty)
__device__ unsigned int       g_tabMin[TS];        // min node index per key
__device__ int                g_firsts[NN];
__device__ int                g_rank[NN];
__device__ int                g_counts[BB * NN];   // per-graph color histogram (4 MB)
__device__ int                g_x64, g_b64;        // dtype flags: 1 if input is int64

__device__ __forceinline__ unsigned long long mix64(unsigned long long v) {
    v ^= v >> 33; v *= 0xFF51AFD7ED558CCDULL;
    v ^= v >> 33; v *= 0xC4CEB9FE1A85EC53ULL;
    v ^= v >> 33; return v;
}

// Load small nonnegative integer from buffer that is either int32[] or int64[] (LE).
__device__ __forceinline__ int load_small(const unsigned int* w, int i, int is64) {
    return (int)(is64 ? w[2 * i] : w[i]);
}

// ---------------- Kd: detect int32 vs int64 input layout ----------------
// Reads only the first 8192 words (32 KB) of each buffer — valid either way.
// int64 values < 2^31 => all odd words are zero.
__global__ void kd_detect(const unsigned int* __restrict__ xw,
                          const unsigned int* __restrict__ bw) {
    __shared__ int sx[256], sb[256];
    int t = threadIdx.x;
    int cx = 0, cb = 0;
    for (int j = t; j < 4096; j += 256) {
        if (xw[2 * j + 1]) cx++;
        if (bw[2 * j + 1]) cb++;
    }
    sx[t] = cx; sb[t] = cb;
    __syncthreads();
    for (int o = 128; o > 0; o >>= 1) {
        if (t < o) { sx[t] += sx[t + o]; sb[t] += sb[t + o]; }
        __syncthreads();
    }
    if (t == 0) { g_x64 = (sx[0] == 0) ? 1 : 0; g_b64 = (sb[0] == 0) ? 1 : 0; }
}

// ---------------- K0: per-launch init (graph replay safe) ----------------
__global__ void k0_init(const unsigned int* __restrict__ xw) {
    int i = blockIdx.x * blockDim.x + threadIdx.x;
    int stride = gridDim.x * blockDim.x;
    int is64 = g_x64;
    for (int j = i; j < BB * NN; j += stride) g_counts[j] = 0;
    for (int j = i; j < TS; j += stride) { g_tabKey[j] = 0ULL; g_tabMin[j] = 0xFFFFFFFFu; }
    for (int j = i; j < NN / 4; j += stride) g_colAnyW[j] = 0u;
    for (int j = i; j < NN; j += stride) {
        int xv = load_small(xw, j, is64);
        g_Kc[j] = (unsigned int)(mix64(0x123456789ABCDEFULL +
                                       (unsigned long long)xv * 0x9E3779B97F4A7C15ULL) >> 16);
    }
}

// ---------------- K1: heavy streaming pass over 1 GB adjacency ----------------
__global__ __launch_bounds__(256) void k1_heavy(const float* __restrict__ adj) {
    __shared__ __align__(16) unsigned char sAny[NN];
    __shared__ unsigned long long sAccRed[8];
    __shared__ unsigned int sDegRed[8];

    int t = threadIdx.x;
    int warp = t >> 5, lane = t & 31;

    uint4* sA4 = (uint4*)sAny;
#pragma unroll
    for (int k = 0; k < 4; k++) sA4[k * 256 + t] = make_uint4(0, 0, 0, 0);
    __syncthreads();

    int row0 = blockIdx.x * RPB;
    const uint4* Kt4 = (const uint4*)g_Kc;

    for (int r = 0; r < RPB; r++) {
        const uint4* arow = (const uint4*)(adj + (size_t)(row0 + r) * NN);
        unsigned long long acc = 0ULL;
        unsigned int deg = 0u;
#pragma unroll
        for (int k = 0; k < 16; k++) {
            int q = k * 256 + t;            // uint4 index; covers columns 4q..4q+3
            uint4 u  = arow[q];
            uint4 kt = Kt4[q];
            acc += (unsigned long long)u.x * kt.x;
            acc += (unsigned long long)u.y * kt.y;
            acc += (unsigned long long)u.z * kt.z;
            acc += (unsigned long long)u.w * kt.w;
            if (u.x) { deg++; sAny[4 * q + 0] = 1; }
            if (u.y) { deg++; sAny[4 * q + 1] = 1; }
            if (u.z) { deg++; sAny[4 * q + 2] = 1; }
            if (u.w) { deg++; sAny[4 * q + 3] = 1; }
        }
#pragma unroll
        for (int o = 16; o > 0; o >>= 1) {
            acc += __shfl_down_sync(0xffffffffu, acc, o);
            deg += __shfl_down_sync(0xffffffffu, deg, o);
        }
        if (lane == 0) { sAccRed[warp] = acc; sDegRed[warp] = deg; }
        __syncthreads();
        if (t == 0) {
            unsigned long long a = 0ULL; unsigned int d = 0u;
#pragma unroll
            for (int w = 0; w < 8; w++) { a += sAccRed[w]; d += sDegRed[w]; }
            g_acc[row0 + r] = a;
            g_deg[row0 + r] = d;
        }
        __syncthreads();
    }

    const uint4* sW = (const uint4*)sAny;
#pragma unroll
    for (int k = 0; k < 4; k++) {
        int q = k * 256 + t;
        uint4 v = sW[q];
        if (v.x) atomicOr(&g_colAnyW[4 * q + 0], v.x);
        if (v.y) atomicOr(&g_colAnyW[4 * q + 1], v.y);
        if (v.z) atomicOr(&g_colAnyW[4 * q + 2], v.z);
        if (v.w) atomicOr(&g_colAnyW[4 * q + 3], v.w);
    }
}

// ---------------- K2: build key, insert into hash table ----------------
__global__ void k2_insert(const unsigned int* __restrict__ xw) {
    int i = blockIdx.x * blockDim.x + threadIdx.x;
    if (i >= NN) return;
    int is64 = g_x64;
    unsigned int deg = g_deg[i];
    unsigned int colw = g_colAnyW[i >> 2];
    bool iso = (deg == 0u) && (((colw >> ((i & 3) * 8)) & 0xFFu) == 0u);
    unsigned long long key = 0ULL;
    if (!iso) {
        int xv = load_small(xw, i, is64);
        unsigned long long h = g_acc[i];
        h = mix64(h ^ ((unsigned long long)deg * 0xD6E8FEB86659FD93ULL));
        h = mix64(h + (unsigned long long)xv * 0xA24BAED4963EE407ULL);
        if (h == 0ULL) h = 0x9E3779B97F4A7C15ULL;
        key = h;
        unsigned int s = (unsigned int)(h >> 32) & (TS - 1);
        for (;;) {
            unsigned long long prev = atomicCAS(&g_tabKey[s], 0ULL, h);
            if (prev == 0ULL || prev == h) { atomicMin(&g_tabMin[s], (unsigned int)i); break; }
            s = (s + 1) & (TS - 1);
        }
    }
    g_key[i] = key;
}

// ---------------- K3: lookup first-occurrence index ----------------
__global__ void k3_lookup() {
    int i = blockIdx.x * blockDim.x + threadIdx.x;
    if (i >= NN) return;
    unsigned long long key = g_key[i];
    int f = -1;
    if (key) {
        unsigned int s = (unsigned int)(key >> 32) & (TS - 1);
        while (g_tabKey[s] != key) s = (s + 1) & (TS - 1);
        f = (int)g_tabMin[s];
    }
    g_firsts[i] = f;
}

// ---------------- K4: rank prefix-scan + colors + histogram counts ----------------
__global__ __launch_bounds__(1024) void k4_scan(const unsigned int* __restrict__ bw,
                                                float* __restrict__ out,
                                                long long out_size) {
    __shared__ int sSum[1024];
    int t = threadIdx.x;
    int base = t * 16;
    int isf[16];
    int local = 0;
#pragma unroll
    for (int k = 0; k < 16; k++) {
        int i = base + k;
        int v = (g_firsts[i] == i) ? 1 : 0;   // iso has firsts == -1, never equal
        isf[k] = v; local += v;
    }
    sSum[t] = local;
    __syncthreads();
    for (int o = 1; o < 1024; o <<= 1) {
        int v = (t >= o) ? sSum[t - o] : 0;
        __syncthreads();
        sSum[t] += v;
        __syncthreads();
    }
    int run = sSum[t] - local;
#pragma unroll
    for (int k = 0; k < 16; k++) { run += isf[k]; g_rank[base + k] = run; }
    __syncthreads();
    int is64 = g_b64;
    long long histElems = (long long)BB * NN;
    bool haveHist = out_size >= histElems;
    long long colorBase = haveHist ? histElems : 0;
#pragma unroll
    for (int k = 0; k < 16; k++) {
        int i = base + k;
        int f = g_firsts[i];
        int c = (f < 0) ? 0 : g_rank[f];
        if (c > 0) {
            int g = load_small(bw, i, is64) & (BB - 1);  // mask: crash-proof
            atomicAdd(&g_counts[g * NN + (c - 1)], 1);
        }
        long long oi = colorBase + i;
        if (oi < out_size) out[oi] = (float)c;           // colors (bounds-checked)
    }
}

// ---------------- K5: per-graph L2 normalization ----------------
__global__ __launch_bounds__(256) void k5_norm(float* __restrict__ out, long long out_size) {
    __shared__ double sred[256];
    int b = blockIdx.x, t = threadIdx.x;
    const int* cnt = g_counts + b * NN;
    double ss = 0.0;
    for (int j = t; j < NN; j += 256) { double v = (double)cnt[j]; ss += v * v; }
    sred[t] = ss; __syncthreads();
#pragma unroll
    for (int o = 128; o > 0; o >>= 1) { if (t < o) sred[t] += sred[t + o]; __syncthreads(); }
    double norm = sqrt(sred[0]);
    for (int j = t; j < NN; j += 256) {
        long long oi = (long long)b * NN + j;
        if (oi < out_size) out[oi] = (float)((double)cnt[j] / norm);
    }
}

// ---------------- launcher ----------------
extern "C" void kernel_launch(void* const* d_in, const int* in_sizes, int n_in,
                              void* d_out, int out_size) {
    // Locate adjacency (the N*N-sized input); remaining inputs keep order: x, batch.
    int iA = -1;
    for (int i = 0; i < n_in; i++)
        if ((long long)in_sizes[i] == (long long)NN * (long long)NN) iA = i;
    if (iA < 0) iA = (n_in > 1) ? 1 : 0;
    int ix = -1, ib = -1;
    for (int i = 0; i < n_in; i++) {
        if (i == iA) continue;
        if (ix < 0) ix = i; else if (ib < 0) ib = i;
    }
    if (ix < 0) ix = 0;
    if (ib < 0) ib = ix;

    const unsigned int* xw  = (const unsigned int*)d_in[ix];
    const float*        adj = (const float*)d_in[iA];
    const unsigned int* bw  = (const unsigned int*)d_in[ib];
    float* out = (float*)d_out;
    long long osz = (long long)out_size;

    kd_detect<<<1, 256>>>(xw, bw);
    k0_init<<<256, 256>>>(xw);
    k1_heavy<<<NN / RPB, 256>>>(adj);
    k2_insert<<<NN / 256, 256>>>(xw);
    k3_lookup<<<NN / 256, 256>>>();
    k4_scan<<<1, 1024>>>(bw, out, osz);
    if (osz >= (long long)BB * NN) k5_norm<<<BB, 256>>>(out, osz);
}

// round 4
// speedup vs baseline: 1.2485x; 1.2485x over previous
#include <cuda_runtime.h>
#include <stdint.h>

#define NN 16384
#define BB 64
#define TS 32768          // hash table slots (2x N, power of 2)

// ---------------- device scratch (static, no allocation) ----------------
__device__ __align__(16) unsigned int g_Kc[NN];    // per-column hash multiplier = f(x[j])
__device__ unsigned long long g_acc[NN];           // per-row neighbor-multiset hash
__device__ unsigned char      g_iso[NN];           // 1 if isolated
__device__ unsigned long long g_key[NN];           // signature key (0 for isolated)
__device__ unsigned long long g_tabKey[TS];        // hash table keys (0 = empty)
__device__ unsigned int       g_tabMin[TS];        // min node index per key
__device__ int                g_firsts[NN];
__device__ int                g_rank[NN];
__device__ int                g_counts[BB * NN];   // per-graph color histogram (4 MB)
__device__ int                g_x64, g_b64;        // dtype flags: 1 if input is int64

__device__ __forceinline__ unsigned long long mix64(unsigned long long v) {
    v ^= v >> 33; v *= 0xFF51AFD7ED558CCDULL;
    v ^= v >> 33; v *= 0xC4CEB9FE1A85EC53ULL;
    v ^= v >> 33; return v;
}

__device__ __forceinline__ int load_small(const unsigned int* w, int i, int is64) {
    return (int)(is64 ? w[2 * i] : w[i]);
}

// ---------------- kd: detect int32 vs int64 input layout ----------------
__global__ void kd_detect(const unsigned int* __restrict__ xw,
                          const unsigned int* __restrict__ bw) {
    __shared__ int sx[256], sb[256];
    int t = threadIdx.x;
    int cx = 0, cb = 0;
    for (int j = t; j < 4096; j += 256) {
        if (xw[2 * j + 1]) cx++;
        if (bw[2 * j + 1]) cb++;
    }
    sx[t] = cx; sb[t] = cb;
    __syncthreads();
    for (int o = 128; o > 0; o >>= 1) {
        if (t < o) { sx[t] += sx[t + o]; sb[t] += sb[t + o]; }
        __syncthreads();
    }
    if (t == 0) { g_x64 = (sx[0] == 0) ? 1 : 0; g_b64 = (sb[0] == 0) ? 1 : 0; }
}

// ---------------- k0a: zero counts + hash table ----------------
__global__ void k0a_zero() {
    int i = blockIdx.x * blockDim.x + threadIdx.x;
    int stride = gridDim.x * blockDim.x;
    for (int j = i; j < BB * NN; j += stride) g_counts[j] = 0;
    for (int j = i; j < TS; j += stride) { g_tabKey[j] = 0ULL; g_tabMin[j] = 0xFFFFFFFFu; }
}

// ---------------- k0b: build per-column multipliers ----------------
__global__ void k0b_kc(const unsigned int* __restrict__ xw) {
    int i = blockIdx.x * blockDim.x + threadIdx.x;
    if (i >= NN) return;
    int xv = load_small(xw, i, g_x64);
    g_Kc[i] = (unsigned int)(mix64(0x123456789ABCDEFULL +
                                   (unsigned long long)xv * 0x9E3779B97F4A7C15ULL) >> 16);
}

// ---------------- k1: heavy pass, warp-per-row, no smem, no syncs ----------------
// acc[i] = sum_j bits(adj[i][j]) * Kc[j]  mod 2^64  (bits in {0, 0x3F800000})
__global__ __launch_bounds__(256) void k1_heavy(const float* __restrict__ adj) {
    int row  = blockIdx.x * 8 + (threadIdx.x >> 5);
    int lane = threadIdx.x & 31;
    const uint4* __restrict__ arow = (const uint4*)(adj + (size_t)row * NN);
    const uint4* __restrict__ kt   = (const uint4*)g_Kc;

    unsigned long long a0 = 0, a1 = 0, a2 = 0, a3 = 0;
    // 4096 uint4 per row; lane-contiguous groups of 32, 4 groups per iter.
#pragma unroll 4
    for (int t = lane; t < 4096; t += 128) {
        uint4 u0 = __ldcs(arow + t);
        uint4 u1 = __ldcs(arow + t + 32);
        uint4 u2 = __ldcs(arow + t + 64);
        uint4 u3 = __ldcs(arow + t + 96);
        uint4 c0 = kt[t];
        uint4 c1 = kt[t + 32];
        uint4 c2 = kt[t + 64];
        uint4 c3 = kt[t + 96];
        a0 += (unsigned long long)u0.x * c0.x + (unsigned long long)u0.y * c0.y
            + (unsigned long long)u0.z * c0.z + (unsigned long long)u0.w * c0.w;
        a1 += (unsigned long long)u1.x * c1.x + (unsigned long long)u1.y * c1.y
            + (unsigned long long)u1.z * c1.z + (unsigned long long)u1.w * c1.w;
        a2 += (unsigned long long)u2.x * c2.x + (unsigned long long)u2.y * c2.y
            + (unsigned long long)u2.z * c2.z + (unsigned long long)u2.w * c2.w;
        a3 += (unsigned long long)u3.x * c3.x + (unsigned long long)u3.y * c3.y
            + (unsigned long long)u3.z * c3.z + (unsigned long long)u3.w * c3.w;
    }
    unsigned long long a = (a0 + a1) + (a2 + a3);
#pragma unroll
    for (int o = 16; o > 0; o >>= 1) a += __shfl_down_sync(0xffffffffu, a, o);
    if (lane == 0) g_acc[row] = a;
}

// ---------------- k_iso: lazy exact isolation check ----------------
// Only rows with acc == 0 are candidates (non-isolated rows hash to 0 w.p. ~2^-41).
// For candidates: exact row + column scan. On this input: zero work.
__global__ void k_iso(const float* __restrict__ adj) {
    int i = blockIdx.x * blockDim.x + threadIdx.x;
    if (i >= NN) return;
    if (g_acc[i] != 0ULL) { g_iso[i] = 0; return; }
    bool any = false;
    const float* rp = adj + (size_t)i * NN;
    for (int j = 0; j < NN && !any; j++) if (rp[j] != 0.0f) any = true;
    for (int r = 0; r < NN && !any; r++) if (adj[(size_t)r * NN + i] != 0.0f) any = true;
    g_iso[i] = any ? 0 : 1;
}

// ---------------- k2: build key, insert into hash table ----------------
__global__ void k2_insert(const unsigned int* __restrict__ xw) {
    int i = blockIdx.x * blockDim.x + threadIdx.x;
    if (i >= NN) return;
    unsigned long long key = 0ULL;
    if (!g_iso[i]) {
        int xv = load_small(xw, i, g_x64);
        unsigned long long h = mix64(g_acc[i] + (unsigned long long)xv * 0xA24BAED4963EE407ULL);
        if (h == 0ULL) h = 0x9E3779B97F4A7C15ULL;
        key = h;
        unsigned int s = (unsigned int)(h >> 32) & (TS - 1);
        for (;;) {
            unsigned long long prev = atomicCAS(&g_tabKey[s], 0ULL, h);
            if (prev == 0ULL || prev == h) { atomicMin(&g_tabMin[s], (unsigned int)i); break; }
            s = (s + 1) & (TS - 1);
        }
    }
    g_key[i] = key;
}

// ---------------- k3: lookup first-occurrence index ----------------
__global__ void k3_lookup() {
    int i = blockIdx.x * blockDim.x + threadIdx.x;
    if (i >= NN) return;
    unsigned long long key = g_key[i];
    int f = -1;
    if (key) {
        unsigned int s = (unsigned int)(key >> 32) & (TS - 1);
        while (g_tabKey[s] != key) s = (s + 1) & (TS - 1);
        f = (int)g_tabMin[s];
    }
    g_firsts[i] = f;
}

// ---------------- k4: rank prefix-scan + colors + histogram counts ----------------
__global__ __launch_bounds__(1024) void k4_scan(const unsigned int* __restrict__ bw,
                                                float* __restrict__ out,
                                                long long out_size) {
    __shared__ int sSum[1024];
    int t = threadIdx.x;
    int base = t * 16;
    int isf[16];
    int local = 0;
#pragma unroll
    for (int k = 0; k < 16; k++) {
        int i = base + k;
        int v = (g_firsts[i] == i) ? 1 : 0;   // iso has firsts == -1, never equal
        isf[k] = v; local += v;
    }
    sSum[t] = local;
    __syncthreads();
    for (int o = 1; o < 1024; o <<= 1) {
        int v = (t >= o) ? sSum[t - o] : 0;
        __syncthreads();
        sSum[t] += v;
        __syncthreads();
    }
    int run = sSum[t] - local;
#pragma unroll
    for (int k = 0; k < 16; k++) { run += isf[k]; g_rank[base + k] = run; }
    __syncthreads();
    int is64 = g_b64;
    long long histElems = (long long)BB * NN;
    bool haveHist = out_size >= histElems;
    long long colorBase = haveHist ? histElems : 0;
#pragma unroll
    for (int k = 0; k < 16; k++) {
        int i = base + k;
        int f = g_firsts[i];
        int c = (f < 0) ? 0 : g_rank[f];
        if (c > 0) {
            int g = load_small(bw, i, is64) & (BB - 1);
            atomicAdd(&g_counts[g * NN + (c - 1)], 1);
        }
        long long oi = colorBase + i;
        if (oi < out_size) out[oi] = (float)c;
    }
}

// ---------------- k5: per-graph L2 normalization ----------------
__global__ __launch_bounds__(256) void k5_norm(float* __restrict__ out, long long out_size) {
    __shared__ double sred[256];
    int b = blockIdx.x, t = threadIdx.x;
    const int* cnt = g_counts + b * NN;
    double ss = 0.0;
    for (int j = t; j < NN; j += 256) { double v = (double)cnt[j]; ss += v * v; }
    sred[t] = ss; __syncthreads();
#pragma unroll
    for (int o = 128; o > 0; o >>= 1) { if (t < o) sred[t] += sred[t + o]; __syncthreads(); }
    double norm = sqrt(sred[0]);
    for (int j = t; j < NN; j += 256) {
        long long oi = (long long)b * NN + j;
        if (oi < out_size) out[oi] = (float)((double)cnt[j] / norm);
    }
}

// ---------------- launcher ----------------
extern "C" void kernel_launch(void* const* d_in, const int* in_sizes, int n_in,
                              void* d_out, int out_size) {
    int iA = -1;
    for (int i = 0; i < n_in; i++)
        if ((long long)in_sizes[i] == (long long)NN * (long long)NN) iA = i;
    if (iA < 0) iA = (n_in > 1) ? 1 : 0;
    int ix = -1, ib = -1;
    for (int i = 0; i < n_in; i++) {
        if (i == iA) continue;
        if (ix < 0) ix = i; else if (ib < 0) ib = i;
    }
    if (ix < 0) ix = 0;
    if (ib < 0) ib = ix;

    const unsigned int* xw  = (const unsigned int*)d_in[ix];
    const float*        adj = (const float*)d_in[iA];
    const unsigned int* bw  = (const unsigned int*)d_in[ib];
    float* out = (float*)d_out;
    long long osz = (long long)out_size;

    kd_detect<<<1, 256>>>(xw, bw);                 // #1
    k0a_zero<<<256, 256>>>();                      // #2
    k0b_kc<<<NN / 256, 256>>>(xw);                 // #3
    k1_heavy<<<NN / 8, 256>>>(adj);                // #4  <- ncu-profiled slot
    k_iso<<<NN / 256, 256>>>(adj);                 // #5
    k2_insert<<<NN / 256, 256>>>(xw);              // #6
    k3_lookup<<<NN / 256, 256>>>();                // #7
    k4_scan<<<1, 1024>>>(bw, out, osz);            // #8
    if (osz >= (long long)BB * NN) k5_norm<<<BB, 256>>>(out, osz);  // #9
}

// round 6
// speedup vs baseline: 1.8187x; 1.4568x over previous
#include <cuda_runtime.h>
#include <stdint.h>

#define NN 16384
#define BB 64
#define TS 32768          // hash table slots (2x N, power of 2)

// ---------------- device scratch (static, no allocation) ----------------
__device__ __align__(16) unsigned int g_Kc[NN];    // per-column hash multiplier = f(x[j])
__device__ unsigned long long g_acc[NN];           // per-row neighbor-multiset hash
__device__ unsigned long long g_key[NN];           // signature key (0 for isolated)
__device__ unsigned long long g_tabKey[TS];        // hash table keys (0 = empty)
__device__ unsigned int       g_tabMin[TS];        // min node index per key
__device__ int                g_firsts[NN];
__device__ int                g_rank[NN];
__device__ int                g_counts[BB * NN];   // per-graph color histogram (4 MB)
__device__ int                g_x64, g_b64;        // dtype flags: 1 if input is int64

__device__ __forceinline__ unsigned long long mix64(unsigned long long v) {
    v ^= v >> 33; v *= 0xFF51AFD7ED558CCDULL;
    v ^= v >> 33; v *= 0xC4CEB9FE1A85EC53ULL;
    v ^= v >> 33; return v;
}

__device__ __forceinline__ int load_small(const unsigned int* w, int i, int is64) {
    return (int)(is64 ? w[2 * i] : w[i]);
}

// ---------------- kd: detect int32 vs int64 input layout ----------------
__global__ void kd_detect(const unsigned int* __restrict__ xw,
                          const unsigned int* __restrict__ bw) {
    __shared__ int sx[256], sb[256];
    int t = threadIdx.x;
    int cx = 0, cb = 0;
    for (int j = t; j < 4096; j += 256) {
        if (xw[2 * j + 1]) cx++;
        if (bw[2 * j + 1]) cb++;
    }
    sx[t] = cx; sb[t] = cb;
    __syncthreads();
    for (int o = 128; o > 0; o >>= 1) {
        if (t < o) { sx[t] += sx[t + o]; sb[t] += sb[t + o]; }
        __syncthreads();
    }
    if (t == 0) { g_x64 = (sx[0] == 0) ? 1 : 0; g_b64 = (sb[0] == 0) ? 1 : 0; }
}

// ---------------- k0: fused zero (counts + table) and Kc build ----------------
__global__ void k0_init(const unsigned int* __restrict__ xw) {
    int i = blockIdx.x * blockDim.x + threadIdx.x;
    int stride = gridDim.x * blockDim.x;     // 65536
    int is64 = g_x64;
    int4 z4 = make_int4(0, 0, 0, 0);
    int4* c4 = (int4*)g_counts;
    for (int j = i; j < BB * NN / 4; j += stride) c4[j] = z4;
    for (int j = i; j < TS; j += stride) { g_tabKey[j] = 0ULL; g_tabMin[j] = 0xFFFFFFFFu; }
    if (i < NN) {
        int xv = load_small(xw, i, is64);
        g_Kc[i] = (unsigned int)(mix64(0x123456789ABCDEFULL +
                                       (unsigned long long)xv * 0x9E3779B97F4A7C15ULL) >> 16);
    }
}

// ---------------- k1: heavy pass, warp-per-row (proven: 80% DRAM) ----------------
__global__ __launch_bounds__(256) void k1_heavy(const float* __restrict__ adj) {
    int row  = blockIdx.x * 8 + (threadIdx.x >> 5);
    int lane = threadIdx.x & 31;
    const uint4* __restrict__ arow = (const uint4*)(adj + (size_t)row * NN);
    const uint4* __restrict__ kt   = (const uint4*)g_Kc;

    unsigned long long a0 = 0, a1 = 0, a2 = 0, a3 = 0;
#pragma unroll 4
    for (int t = lane; t < 4096; t += 128) {
        uint4 u0 = __ldcs(arow + t);
        uint4 u1 = __ldcs(arow + t + 32);
        uint4 u2 = __ldcs(arow + t + 64);
        uint4 u3 = __ldcs(arow + t + 96);
        uint4 c0 = kt[t];
        uint4 c1 = kt[t + 32];
        uint4 c2 = kt[t + 64];
        uint4 c3 = kt[t + 96];
        a0 += (unsigned long long)u0.x * c0.x + (unsigned long long)u0.y * c0.y
            + (unsigned long long)u0.z * c0.z + (unsigned long long)u0.w * c0.w;
        a1 += (unsigned long long)u1.x * c1.x + (unsigned long long)u1.y * c1.y
            + (unsigned long long)u1.z * c1.z + (unsigned long long)u1.w * c1.w;
        a2 += (unsigned long long)u2.x * c2.x + (unsigned long long)u2.y * c2.y
            + (unsigned long long)u2.z * c2.z + (unsigned long long)u2.w * c2.w;
        a3 += (unsigned long long)u3.x * c3.x + (unsigned long long)u3.y * c3.y
            + (unsigned long long)u3.z * c3.z + (unsigned long long)u3.w * c3.w;
    }
    unsigned long long a = (a0 + a1) + (a2 + a3);
#pragma unroll
    for (int o = 16; o > 0; o >>= 1) a += __shfl_down_sync(0xffffffffu, a, o);
    if (lane == 0) g_acc[row] = a;
}

// ---------------- k2: key build + hash-table insert (+lazy exact iso) ----------------
// acc == 0 for a non-isolated row w.p. ~2^-41; only then do the exact scan.
__global__ void k2_insert(const unsigned int* __restrict__ xw,
                          const float* __restrict__ adj) {
    int i = blockIdx.x * blockDim.x + threadIdx.x;
    if (i >= NN) return;
    unsigned long long acc = g_acc[i];
    bool iso = false;
    if (acc == 0ULL) {                        // candidate: verify exactly
        bool any = false;
        const float* rp = adj + (size_t)i * NN;
        for (int j = 0; j < NN && !any; j++) if (rp[j] != 0.0f) any = true;
        for (int r = 0; r < NN && !any; r++) if (adj[(size_t)r * NN + i] != 0.0f) any = true;
        iso = !any;
    }
    unsigned long long key = 0ULL;
    if (!iso) {
        int xv = load_small(xw, i, g_x64);
        unsigned long long h = mix64(acc + (unsigned long long)xv * 0xA24BAED4963EE407ULL);
        if (h == 0ULL) h = 0x9E3779B97F4A7C15ULL;
        key = h;
        unsigned int s = (unsigned int)(h >> 32) & (TS - 1);
        for (;;) {
            unsigned long long prev = atomicCAS(&g_tabKey[s], 0ULL, h);
            if (prev == 0ULL || prev == h) { atomicMin(&g_tabMin[s], (unsigned int)i); break; }
            s = (s + 1) & (TS - 1);
        }
    }
    g_key[i] = key;
}

// ---------------- k3: lookup first-occurrence index ----------------
__global__ void k3_lookup() {
    int i = blockIdx.x * blockDim.x + threadIdx.x;
    if (i >= NN) return;
    unsigned long long key = g_key[i];
    int f = -1;
    if (key) {
        unsigned int s = (unsigned int)(key >> 32) & (TS - 1);
        while (g_tabKey[s] != key) s = (s + 1) & (TS - 1);
        f = (int)g_tabMin[s];
    }
    g_firsts[i] = f;
}

// ---------------- k4a: rank prefix-scan only (single block) ----------------
__global__ __launch_bounds__(1024) void k4a_rank() {
    __shared__ int sSum[1024];
    int t = threadIdx.x;
    int base = t * 16;
    int isf[16];
    int local = 0;
#pragma unroll
    for (int k = 0; k < 16; k++) {
        int i = base + k;
        int v = (g_firsts[i] == i) ? 1 : 0;   // iso: firsts == -1, never equal
        isf[k] = v; local += v;
    }
    sSum[t] = local;
    __syncthreads();
    for (int o = 1; o < 1024; o <<= 1) {
        int v = (t >= o) ? sSum[t - o] : 0;
        __syncthreads();
        sSum[t] += v;
        __syncthreads();
    }
    int run = sSum[t] - local;
#pragma unroll
    for (int k = 0; k < 16; k++) { run += isf[k]; g_rank[base + k] = run; }
}

// ---------------- k4b: colors + histogram counts (parallel) ----------------
__global__ void k4b_emit(const unsigned int* __restrict__ bw,
                         float* __restrict__ out, long long out_size) {
    int i = blockIdx.x * blockDim.x + threadIdx.x;
    if (i >= NN) return;
    int f = g_firsts[i];
    int c = (f < 0) ? 0 : g_rank[f];
    if (c > 0) {
        int g = load_small(bw, i, g_b64) & (BB - 1);
        atomicAdd(&g_counts[g * NN + (c - 1)], 1);
    }
    long long histElems = (long long)BB * NN;
    long long colorBase = (out_size >= histElems) ? histElems : 0;
    long long oi = colorBase + i;
    if (oi < out_size) out[oi] = (float)c;
}

// ---------------- k5: per-graph L2 normalization ----------------
__global__ __launch_bounds__(512) void k5_norm(float* __restrict__ out, long long out_size) {
    __shared__ double sred[512];
    int b = blockIdx.x, t = threadIdx.x;
    const int4* cnt4 = (const int4*)(g_counts + b * NN);
    double ss = 0.0;
    for (int j = t; j < NN / 4; j += 512) {
        int4 v = cnt4[j];
        ss += (double)v.x * v.x + (double)v.y * v.y
            + (double)v.z * v.z + (double)v.w * v.w;
    }
    sred[t] = ss; __syncthreads();
#pragma unroll
    for (int o = 256; o > 0; o >>= 1) { if (t < o) sred[t] += sred[t + o]; __syncthreads(); }
    double inv = 1.0 / sqrt(sred[0]);        // 0 -> inf -> NaN outputs, matches reference
    if ((long long)(b + 1) * NN <= out_size) {
        float4* o4 = (float4*)(out + (size_t)b * NN);
        for (int j = t; j < NN / 4; j += 512) {
            int4 v = cnt4[j];
            float4 w;
            w.x = (float)((double)v.x * inv);
            w.y = (float)((double)v.y * inv);
            w.z = (float)((double)v.z * inv);
            w.w = (float)((double)v.w * inv);
            o4[j] = w;
        }
    }
}

// ---------------- launcher ----------------
extern "C" void kernel_launch(void* const* d_in, const int* in_sizes, int n_in,
                              void* d_out, int out_size) {
    int iA = -1;
    for (int i = 0; i < n_in; i++)
        if ((long long)in_sizes[i] == (long long)NN * (long long)NN) iA = i;
    if (iA < 0) iA = (n_in > 1) ? 1 : 0;
    int ix = -1, ib = -1;
    for (int i = 0; i < n_in; i++) {
        if (i == iA) continue;
        if (ix < 0) ix = i; else if (ib < 0) ib = i;
    }
    if (ix < 0) ix = 0;
    if (ib < 0) ib = ix;

    const unsigned int* xw  = (const unsigned int*)d_in[ix];
    const float*        adj = (const float*)d_in[iA];
    const unsigned int* bw  = (const unsigned int*)d_in[ib];
    float* out = (float*)d_out;
    long long osz = (long long)out_size;

    kd_detect<<<1, 256>>>(xw, bw);                    // #1
    k0_init<<<256, 256>>>(xw);                        // #2
    k1_heavy<<<NN / 8, 256>>>(adj);                   // #3
    k2_insert<<<NN / 256, 256>>>(xw, adj);            // #4
    k3_lookup<<<NN / 256, 256>>>();                   // #5
    k4a_rank<<<1, 1024>>>();                          // #6
    k4b_emit<<<NN / 256, 256>>>(bw, out, osz);        // #7
    if (osz >= (long long)BB * NN) k5_norm<<<BB, 512>>>(out, osz);  // #8
}

// round 7
// speedup vs baseline: 1.8948x; 1.0418x over previous
#include <cuda_runtime.h>
#include <stdint.h>

#define NN 16384
#define BB 64
#define TS 32768          // hash table slots (2x N, power of 2)
#define PREB 128          // blocks in pre kernel
#define POSTB 64          // blocks in post kernel

// ---------------- device scratch (static, no allocation) ----------------
__device__ __align__(16) unsigned int g_Kc[NN];    // per-column hash multiplier = f(x[j])
__device__ unsigned long long g_acc[NN];           // per-row neighbor-multiset hash
__device__ unsigned long long g_tabKey[TS];        // hash table keys (0 = empty)
__device__ unsigned int       g_tabMin[TS];        // min node index per key
__device__ int                g_firsts[NN];
__device__ int                g_rank[NN];
__device__ int                g_bsum[POSTB];       // per-block is_first totals
__device__ int                g_counts[BB * NN];   // per-graph color histogram (4 MB)
__device__ int                g_x64, g_b64;        // dtype flags: 1 if input is int64
__device__ unsigned int       g_barCnt[8];         // grid-barrier arrive counters
__device__ unsigned int       g_barGen[8];         // grid-barrier generations (monotonic)

__device__ __forceinline__ unsigned long long mix64(unsigned long long v) {
    v ^= v >> 33; v *= 0xFF51AFD7ED558CCDULL;
    v ^= v >> 33; v *= 0xC4CEB9FE1A85EC53ULL;
    v ^= v >> 33; return v;
}

__device__ __forceinline__ int load_small(const unsigned int* w, int i, int is64) {
    return (int)(is64 ? w[2 * i] : w[i]);
}

// Software grid barrier (sense via monotonic generation; replay-safe).
__device__ __forceinline__ void gridBarrier(int id, unsigned int nblocks) {
    __syncthreads();
    if (threadIdx.x == 0) {
        __threadfence();
        unsigned int gen = atomicAdd(&g_barGen[id], 0u);
        if (atomicAdd(&g_barCnt[id], 1u) == nblocks - 1u) {
            g_barCnt[id] = 0u;
            __threadfence();
            atomicAdd(&g_barGen[id], 1u);           // release
        } else {
            while (atomicAdd(&g_barGen[id], 0u) == gen) __nanosleep(32);
        }
        __threadfence();
    }
    __syncthreads();
}

// ---------------- k_pre: detect dtypes + zero scratch + build Kc ----------------
__global__ __launch_bounds__(256) void k_pre(const unsigned int* __restrict__ xw,
                                             const unsigned int* __restrict__ bw) {
    int t = threadIdx.x;
    int gi = blockIdx.x * 256 + t;
    int stride = PREB * 256;                        // 32768

    if (blockIdx.x == 0) {
        // dtype detection: odd 32-bit words of first 4096 elements are all zero iff int64
        __shared__ int sx[256], sb[256];
        int cx = 0, cb = 0;
        for (int j = t; j < 4096; j += 256) {
            if (xw[2 * j + 1]) cx++;
            if (bw[2 * j + 1]) cb++;
        }
        sx[t] = cx; sb[t] = cb;
        __syncthreads();
        for (int o = 128; o > 0; o >>= 1) {
            if (t < o) { sx[t] += sx[t + o]; sb[t] += sb[t + o]; }
            __syncthreads();
        }
        if (t == 0) { g_x64 = (sx[0] == 0) ? 1 : 0; g_b64 = (sb[0] == 0) ? 1 : 0; }
    }

    // all blocks: zero counts + hash table
    int4 z4 = make_int4(0, 0, 0, 0);
    int4* c4 = (int4*)g_counts;
    for (int j = gi; j < BB * NN / 4; j += stride) c4[j] = z4;
    for (int j = gi; j < TS; j += stride) { g_tabKey[j] = 0ULL; g_tabMin[j] = 0xFFFFFFFFu; }

    gridBarrier(0, PREB);

    if (gi < NN) {
        int xv = load_small(xw, gi, g_x64);
        g_Kc[gi] = (unsigned int)(mix64(0x123456789ABCDEFULL +
                                        (unsigned long long)xv * 0x9E3779B97F4A7C15ULL) >> 16);
    }
}

// ---------------- k1: heavy pass, warp-per-row (proven: 80% DRAM) ----------------
__global__ __launch_bounds__(256) void k1_heavy(const float* __restrict__ adj) {
    int row  = blockIdx.x * 8 + (threadIdx.x >> 5);
    int lane = threadIdx.x & 31;
    const uint4* __restrict__ arow = (const uint4*)(adj + (size_t)row * NN);
    const uint4* __restrict__ kt   = (const uint4*)g_Kc;

    unsigned long long a0 = 0, a1 = 0, a2 = 0, a3 = 0;
#pragma unroll 4
    for (int t = lane; t < 4096; t += 128) {
        uint4 u0 = __ldcs(arow + t);
        uint4 u1 = __ldcs(arow + t + 32);
        uint4 u2 = __ldcs(arow + t + 64);
        uint4 u3 = __ldcs(arow + t + 96);
        uint4 c0 = kt[t];
        uint4 c1 = kt[t + 32];
        uint4 c2 = kt[t + 64];
        uint4 c3 = kt[t + 96];
        a0 += (unsigned long long)u0.x * c0.x + (unsigned long long)u0.y * c0.y
            + (unsigned long long)u0.z * c0.z + (unsigned long long)u0.w * c0.w;
        a1 += (unsigned long long)u1.x * c1.x + (unsigned long long)u1.y * c1.y
            + (unsigned long long)u1.z * c1.z + (unsigned long long)u1.w * c1.w;
        a2 += (unsigned long long)u2.x * c2.x + (unsigned long long)u2.y * c2.y
            + (unsigned long long)u2.z * c2.z + (unsigned long long)u2.w * c2.w;
        a3 += (unsigned long long)u3.x * c3.x + (unsigned long long)u3.y * c3.y
            + (unsigned long long)u3.z * c3.z + (unsigned long long)u3.w * c3.w;
    }
    unsigned long long a = (a0 + a1) + (a2 + a3);
#pragma unroll
    for (int o = 16; o > 0; o >>= 1) a += __shfl_down_sync(0xffffffffu, a, o);
    if (lane == 0) g_acc[row] = a;
}

// ---------------- k_post: insert + lookup + rank + emit + norm in ONE kernel ----------------
__global__ __launch_bounds__(256) void k_post(const unsigned int* __restrict__ xw,
                                              const unsigned int* __restrict__ bw,
                                              const float* __restrict__ adj,
                                              float* __restrict__ out,
                                              long long out_size) {
    __shared__ int sScan[256];
    int t = threadIdx.x;
    int blk = blockIdx.x;
    int i = blk * 256 + t;                           // node id (POSTB*256 == NN)

    // ---- phase 1: key build + hash-table insert (+lazy exact iso) ----
    unsigned long long acc = g_acc[i];
    bool iso = false;
    if (acc == 0ULL) {                               // w.p. ~2^-41 for non-isolated
        bool any = false;
        const float* rp = adj + (size_t)i * NN;
        for (int j = 0; j < NN && !any; j++) if (rp[j] != 0.0f) any = true;
        for (int r = 0; r < NN && !any; r++) if (adj[(size_t)r * NN + i] != 0.0f) any = true;
        iso = !any;
    }
    unsigned long long key = 0ULL;
    if (!iso) {
        int xv = load_small(xw, i, g_x64);
        unsigned long long h = mix64(acc + (unsigned long long)xv * 0xA24BAED4963EE407ULL);
        if (h == 0ULL) h = 0x9E3779B97F4A7C15ULL;
        key = h;
        unsigned int s = (unsigned int)(h >> 32) & (TS - 1);
        for (;;) {
            unsigned long long prev = atomicCAS(&g_tabKey[s], 0ULL, h);
            if (prev == 0ULL || prev == h) { atomicMin(&g_tabMin[s], (unsigned int)i); break; }
            s = (s + 1) & (TS - 1);
        }
    }
    gridBarrier(1, POSTB);

    // ---- phase 2: lookup first-occurrence + block scan of is_first ----
    int f = -1;
    if (key) {
        unsigned int s = (unsigned int)(key >> 32) & (TS - 1);
        while (g_tabKey[s] != key) s = (s + 1) & (TS - 1);
        f = (int)g_tabMin[s];
    }
    g_firsts[i] = f;
    int isf = (f == i) ? 1 : 0;
    sScan[t] = isf;
    __syncthreads();
#pragma unroll
    for (int o = 1; o < 256; o <<= 1) {
        int v = (t >= o) ? sScan[t - o] : 0;
        __syncthreads();
        sScan[t] += v;
        __syncthreads();
    }
    int incl = sScan[t];                             // inclusive in-block prefix
    if (t == 255) g_bsum[blk] = incl;
    gridBarrier(2, POSTB);

    // ---- phase 3: cross-block rank offsets ----
    int off = 0;
    for (int b = 0; b < POSTB; b++) { if (b < blk) off += g_bsum[b]; }
    g_rank[i] = off + incl;                          // inclusive rank among firsts
    gridBarrier(3, POSTB);

    // ---- phase 4: emit colors + histogram counts ----
    int c = (f < 0) ? 0 : g_rank[f];
    if (c > 0) {
        int g = load_small(bw, i, g_b64) & (BB - 1);
        atomicAdd(&g_counts[g * NN + (c - 1)], 1);
    }
    long long histElems = (long long)BB * NN;
    long long colorBase = (out_size >= histElems) ? histElems : 0;
    long long oi = colorBase + i;
    if (oi < out_size) out[oi] = (float)c;
    gridBarrier(4, POSTB);                           // fence inside barrier orders atomics

    // ---- phase 5: per-graph L2 normalization (block blk <-> graph blk) ----
    {
        __shared__ double sred[256];
        const int4* cnt4 = (const int4*)(g_counts + blk * NN);
        double ss = 0.0;
#pragma unroll
        for (int j = t; j < NN / 4; j += 256) {
            int4 v = cnt4[j];
            ss += (double)v.x * v.x + (double)v.y * v.y
                + (double)v.z * v.z + (double)v.w * v.w;
        }
        sred[t] = ss; __syncthreads();
#pragma unroll
        for (int o = 128; o > 0; o >>= 1) { if (t < o) sred[t] += sred[t + o]; __syncthreads(); }
        double inv = 1.0 / sqrt(sred[0]);            // 0 -> inf -> NaN, matches reference
        if ((long long)(blk + 1) * NN <= out_size) {
            float4* o4 = (float4*)(out + (size_t)blk * NN);
            for (int j = t; j < NN / 4; j += 256) {
                int4 v = cnt4[j];
                float4 w;
                w.x = (float)((double)v.x * inv);
                w.y = (float)((double)v.y * inv);
                w.z = (float)((double)v.z * inv);
                w.w = (float)((double)v.w * inv);
                o4[j] = w;
            }
        }
    }
}

// ---------------- launcher ----------------
extern "C" void kernel_launch(void* const* d_in, const int* in_sizes, int n_in,
                              void* d_out, int out_size) {
    int iA = -1;
    for (int i = 0; i < n_in; i++)
        if ((long long)in_sizes[i] == (long long)NN * (long long)NN) iA = i;
    if (iA < 0) iA = (n_in > 1) ? 1 : 0;
    int ix = -1, ib = -1;
    for (int i = 0; i < n_in; i++) {
        if (i == iA) continue;
        if (ix < 0) ix = i; else if (ib < 0) ib = i;
    }
    if (ix < 0) ix = 0;
    if (ib < 0) ib = ix;

    const unsigned int* xw  = (const unsigned int*)d_in[ix];
    const float*        adj = (const float*)d_in[iA];
    const unsigned int* bw  = (const unsigned int*)d_in[ib];
    float* out = (float*)d_out;
    long long osz = (long long)out_size;

    k_pre<<<PREB, 256>>>(xw, bw);                    // #1
    k1_heavy<<<NN / 8, 256>>>(adj);                  // #2
    k_post<<<POSTB, 256>>>(xw, bw, adj, out, osz);   // #3
}

// round 8
// speedup vs baseline: 1.8974x; 1.0014x over previous
#include <cuda_runtime.h>
#include <stdint.h>

#define NN 16384
#define BB 64
#define TS 32768          // hash table slots (2x N, power of 2)
#define PREB 64           // blocks in pre kernel (one thread per node)
#define POSTB 64          // blocks in post kernel
#define K1B (NN / 8)      // 2048 blocks in heavy kernel

// ---------------- device scratch (static, no allocation) ----------------
__device__ __align__(16) unsigned int g_Kc[NN];    // per-column hash multiplier = f(x[j])
__device__ unsigned long long g_acc[NN];           // per-row neighbor-multiset hash
__device__ __align__(16) unsigned long long g_tabKey[TS];  // hash table keys (0 = empty)
__device__ __align__(16) unsigned int g_tabMin[TS];        // min node index per key
__device__ int                g_firsts[NN];
__device__ int                g_rank[NN];
__device__ int                g_bsum[POSTB];       // per-block is_first totals
__device__ __align__(16) int  g_counts[BB * NN];   // per-graph color histogram (4 MB)
__device__ int                g_x64, g_b64;        // dtype flags: 1 if input is int64
__device__ unsigned int       g_barCnt[8];         // grid-barrier arrive counters
__device__ unsigned int       g_barGen[8];         // grid-barrier generations (monotonic)

__device__ __forceinline__ unsigned long long mix64(unsigned long long v) {
    v ^= v >> 33; v *= 0xFF51AFD7ED558CCDULL;
    v ^= v >> 33; v *= 0xC4CEB9FE1A85EC53ULL;
    v ^= v >> 33; return v;
}

__device__ __forceinline__ int load_small(const unsigned int* w, int i, int is64) {
    return (int)(is64 ? w[2 * i] : w[i]);
}

// Software grid barrier (sense via monotonic generation; replay-safe).
__device__ __forceinline__ void gridBarrier(int id, unsigned int nblocks) {
    __syncthreads();
    if (threadIdx.x == 0) {
        __threadfence();
        unsigned int gen = atomicAdd(&g_barGen[id], 0u);
        if (atomicAdd(&g_barCnt[id], 1u) == nblocks - 1u) {
            g_barCnt[id] = 0u;
            __threadfence();
            atomicAdd(&g_barGen[id], 1u);           // release
        } else {
            while (atomicAdd(&g_barGen[id], 0u) == gen) { }   // tight poll (L2 atomic)
        }
        __threadfence();
    }
    __syncthreads();
}

// ---------------- k_pre: per-block dtype detect + build Kc (no grid barrier) ----------------
__global__ __launch_bounds__(256) void k_pre(const unsigned int* __restrict__ xw,
                                             const unsigned int* __restrict__ bw) {
    __shared__ int sx[256];
    int t = threadIdx.x;
    int i = blockIdx.x * 256 + t;                    // node id (PREB*256 == NN)

    // per-block x dtype detection (16 KB of odd words; L2-hot after first block)
    int cx = 0;
    for (int j = t; j < 4096; j += 256) if (xw[2 * j + 1]) cx++;
    sx[t] = cx;
    __syncthreads();
#pragma unroll
    for (int o = 128; o > 0; o >>= 1) { if (t < o) sx[t] += sx[t + o]; __syncthreads(); }
    int x64 = (sx[0] == 0) ? 1 : 0;

    if (blockIdx.x == 0) {
        // block 0 additionally detects batch dtype and publishes flags for k_post
        int cb = 0;
        for (int j = t; j < 4096; j += 256) if (bw[2 * j + 1]) cb++;
        sx[t] = cb;
        __syncthreads();
#pragma unroll
        for (int o = 128; o > 0; o >>= 1) { if (t < o) sx[t] += sx[t + o]; __syncthreads(); }
        if (t == 0) { g_b64 = (sx[0] == 0) ? 1 : 0; g_x64 = x64; }
    }

    int xv = load_small(xw, i, x64);
    g_Kc[i] = (unsigned int)(mix64(0x123456789ABCDEFULL +
                                   (unsigned long long)xv * 0x9E3779B97F4A7C15ULL) >> 16);
}

// ---------------- k1: heavy pass, warp-per-row + hidden scratch zeroing ----------------
__global__ __launch_bounds__(256) void k1_heavy(const float* __restrict__ adj) {
    int blk = blockIdx.x;
    int t = threadIdx.x;

    // hidden zeroing: each block clears its slice of counts + hash table.
    // counts: 262144 int4 / 2048 blocks = 128 per block; table: 16 slots per block.
    {
        int4* c4 = (int4*)g_counts;
        if (t < 128) c4[blk * 128 + t] = make_int4(0, 0, 0, 0);
        if (t >= 128 && t < 144) {
            int s = blk * 16 + (t - 128);
            g_tabKey[s] = 0ULL;
            g_tabMin[s] = 0xFFFFFFFFu;
        }
    }

    int row  = blk * 8 + (t >> 5);
    int lane = t & 31;
    const uint4* __restrict__ arow = (const uint4*)(adj + (size_t)row * NN);
    const uint4* __restrict__ kt   = (const uint4*)g_Kc;

    unsigned long long a0 = 0, a1 = 0, a2 = 0, a3 = 0;
#pragma unroll 4
    for (int q = lane; q < 4096; q += 128) {
        uint4 u0 = __ldcs(arow + q);
        uint4 u1 = __ldcs(arow + q + 32);
        uint4 u2 = __ldcs(arow + q + 64);
        uint4 u3 = __ldcs(arow + q + 96);
        uint4 c0 = kt[q];
        uint4 c1 = kt[q + 32];
        uint4 c2 = kt[q + 64];
        uint4 c3 = kt[q + 96];
        a0 += (unsigned long long)u0.x * c0.x + (unsigned long long)u0.y * c0.y
            + (unsigned long long)u0.z * c0.z + (unsigned long long)u0.w * c0.w;
        a1 += (unsigned long long)u1.x * c1.x + (unsigned long long)u1.y * c1.y
            + (unsigned long long)u1.z * c1.z + (unsigned long long)u1.w * c1.w;
        a2 += (unsigned long long)u2.x * c2.x + (unsigned long long)u2.y * c2.y
            + (unsigned long long)u2.z * c2.z + (unsigned long long)u2.w * c2.w;
        a3 += (unsigned long long)u3.x * c3.x + (unsigned long long)u3.y * c3.y
            + (unsigned long long)u3.z * c3.z + (unsigned long long)u3.w * c3.w;
    }
    unsigned long long a = (a0 + a1) + (a2 + a3);
#pragma unroll
    for (int o = 16; o > 0; o >>= 1) a += __shfl_down_sync(0xffffffffu, a, o);
    if (lane == 0) g_acc[row] = a;
}

// ---------------- k_post: insert + lookup + rank + emit + norm in ONE kernel ----------------
__global__ __launch_bounds__(256) void k_post(const unsigned int* __restrict__ xw,
                                              const unsigned int* __restrict__ bw,
                                              const float* __restrict__ adj,
                                              float* __restrict__ out,
                                              long long out_size) {
    __shared__ int sScan[256];
    int t = threadIdx.x;
    int blk = blockIdx.x;
    int i = blk * 256 + t;                           // node id (POSTB*256 == NN)

    // ---- phase 1: key build + hash-table insert (+lazy exact iso) ----
    unsigned long long acc = g_acc[i];
    bool iso = false;
    if (acc == 0ULL) {                               // w.p. ~2^-41 for non-isolated
        bool any = false;
        const float* rp = adj + (size_t)i * NN;
        for (int j = 0; j < NN && !any; j++) if (rp[j] != 0.0f) any = true;
        for (int r = 0; r < NN && !any; r++) if (adj[(size_t)r * NN + i] != 0.0f) any = true;
        iso = !any;
    }
    unsigned long long key = 0ULL;
    if (!iso) {
        int xv = load_small(xw, i, g_x64);
        unsigned long long h = mix64(acc + (unsigned long long)xv * 0xA24BAED4963EE407ULL);
        if (h == 0ULL) h = 0x9E3779B97F4A7C15ULL;
        key = h;
        unsigned int s = (unsigned int)(h >> 32) & (TS - 1);
        for (;;) {
            unsigned long long prev = atomicCAS(&g_tabKey[s], 0ULL, h);
            if (prev == 0ULL || prev == h) { atomicMin(&g_tabMin[s], (unsigned int)i); break; }
            s = (s + 1) & (TS - 1);
        }
    }
    gridBarrier(1, POSTB);

    // ---- phase 2: lookup first-occurrence + block scan of is_first ----
    int f = -1;
    if (key) {
        unsigned int s = (unsigned int)(key >> 32) & (TS - 1);
        while (g_tabKey[s] != key) s = (s + 1) & (TS - 1);
        f = (int)g_tabMin[s];
    }
    g_firsts[i] = f;
    int isf = (f == i) ? 1 : 0;
    sScan[t] = isf;
    __syncthreads();
#pragma unroll
    for (int o = 1; o < 256; o <<= 1) {
        int v = (t >= o) ? sScan[t - o] : 0;
        __syncthreads();
        sScan[t] += v;
        __syncthreads();
    }
    int incl = sScan[t];                             // inclusive in-block prefix
    if (t == 255) g_bsum[blk] = incl;
    gridBarrier(2, POSTB);

    // ---- phase 3: cross-block rank offsets ----
    int off = 0;
#pragma unroll
    for (int b = 0; b < POSTB; b++) { if (b < blk) off += g_bsum[b]; }
    g_rank[i] = off + incl;                          // inclusive rank among firsts
    gridBarrier(3, POSTB);

    // ---- phase 4: emit colors + histogram counts ----
    int c = (f < 0) ? 0 : g_rank[f];
    if (c > 0) {
        int g = load_small(bw, i, g_b64) & (BB - 1);
        atomicAdd(&g_counts[g * NN + (c - 1)], 1);
    }
    long long histElems = (long long)BB * NN;
    long long colorBase = (out_size >= histElems) ? histElems : 0;
    long long oi = colorBase + i;
    if (oi < out_size) out[oi] = (float)c;
    gridBarrier(4, POSTB);                           // fence inside barrier orders atomics

    // ---- phase 5: per-graph L2 normalization (block blk <-> graph blk) ----
    {
        __shared__ double sred[256];
        const int4* cnt4 = (const int4*)(g_counts + blk * NN);
        double ss = 0.0;
#pragma unroll
        for (int j = t; j < NN / 4; j += 256) {
            int4 v = cnt4[j];
            ss += (double)v.x * v.x + (double)v.y * v.y
                + (double)v.z * v.z + (double)v.w * v.w;
        }
        sred[t] = ss; __syncthreads();
#pragma unroll
        for (int o = 128; o > 0; o >>= 1) { if (t < o) sred[t] += sred[t + o]; __syncthreads(); }
        double inv = 1.0 / sqrt(sred[0]);            // 0 -> inf -> NaN, matches reference
        if ((long long)(blk + 1) * NN <= out_size) {
            float4* o4 = (float4*)(out + (size_t)blk * NN);
            for (int j = t; j < NN / 4; j += 256) {
                int4 v = cnt4[j];
                float4 w;
                w.x = (float)((double)v.x * inv);
                w.y = (float)((double)v.y * inv);
                w.z = (float)((double)v.z * inv);
                w.w = (float)((double)v.w * inv);
                o4[j] = w;
            }
        }
    }
}

// ---------------- launcher ----------------
extern "C" void kernel_launch(void* const* d_in, const int* in_sizes, int n_in,
                              void* d_out, int out_size) {
    int iA = -1;
    for (int i = 0; i < n_in; i++)
        if ((long long)in_sizes[i] == (long long)NN * (long long)NN) iA = i;
    if (iA < 0) iA = (n_in > 1) ? 1 : 0;
    int ix = -1, ib = -1;
    for (int i = 0; i < n_in; i++) {
        if (i == iA) continue;
        if (ix < 0) ix = i; else if (ib < 0) ib = i;
    }
    if (ix < 0) ix = 0;
    if (ib < 0) ib = ix;

    const unsigned int* xw  = (const unsigned int*)d_in[ix];
    const float*        adj = (const float*)d_in[iA];
    const unsigned int* bw  = (const unsigned int*)d_in[ib];
    float* out = (float*)d_out;
    long long osz = (long long)out_size;

    k_pre<<<PREB, 256>>>(xw, bw);                    // #1  (~3-4 us)
    k1_heavy<<<K1B, 256>>>(adj);                     // #2  (~170 us, DRAM-bound)
    k_post<<<POSTB, 256>>>(xw, bw, adj, out, osz);   // #3
}

// round 9
// speedup vs baseline: 1.8996x; 1.0011x over previous
#include <cuda_runtime.h>
#include <stdint.h>

#define NN 16384
#define BB 64
#define TS 32768          // hash table slots (2x N, power of 2)
#define PREB 64           // blocks in pre kernel (one thread per node)
#define POSTB 64          // blocks in post kernel
#define K1B (NN / 8)      // 2048 blocks in heavy kernel

// ---------------- device scratch (static, no allocation) ----------------
__device__ __align__(16) unsigned int g_Kc[NN];    // per-column hash multiplier = f(x[j])
__device__ unsigned long long g_acc[NN];           // per-row neighbor-multiset hash
__device__ __align__(16) unsigned long long g_tab[TS]; // fused slot: key_hi50 | min node idx (0=empty)
__device__ int                g_firsts[NN];
__device__ int                g_rank[NN];          // in-block inclusive prefix of is_first
__device__ int                g_bsum[POSTB];       // per-block is_first totals
__device__ __align__(16) int  g_counts[BB * NN];   // per-graph color histogram (4 MB)
__device__ int                g_x64, g_b64;        // dtype flags: 1 if input is int64
__device__ unsigned int       g_barCnt[8];         // grid-barrier arrive counters
__device__ unsigned int       g_barGen[8];         // grid-barrier generations (monotonic)

__device__ __forceinline__ unsigned long long mix64(unsigned long long v) {
    v ^= v >> 33; v *= 0xFF51AFD7ED558CCDULL;
    v ^= v >> 33; v *= 0xC4CEB9FE1A85EC53ULL;
    v ^= v >> 33; return v;
}

__device__ __forceinline__ int load_small(const unsigned int* w, int i, int is64) {
    return (int)(is64 ? w[2 * i] : w[i]);
}

// Software grid barrier (sense via monotonic generation; replay-safe).
__device__ __forceinline__ void gridBarrier(int id, unsigned int nblocks) {
    __syncthreads();
    if (threadIdx.x == 0) {
        __threadfence();
        unsigned int gen = atomicAdd(&g_barGen[id], 0u);
        if (atomicAdd(&g_barCnt[id], 1u) == nblocks - 1u) {
            g_barCnt[id] = 0u;
            __threadfence();
            atomicAdd(&g_barGen[id], 1u);           // release
        } else {
            while (atomicAdd(&g_barGen[id], 0u) == gen) { }
        }
        __threadfence();
    }
    __syncthreads();
}

// ---------------- k_pre: per-block dtype detect + build Kc ----------------
__global__ __launch_bounds__(256) void k_pre(const unsigned int* __restrict__ xw,
                                             const unsigned int* __restrict__ bw) {
    __shared__ int sx[256];
    int t = threadIdx.x;
    int i = blockIdx.x * 256 + t;                    // node id (PREB*256 == NN)

    int cx = 0;
    for (int j = t; j < 4096; j += 256) if (xw[2 * j + 1]) cx++;
    sx[t] = cx;
    __syncthreads();
#pragma unroll
    for (int o = 128; o > 0; o >>= 1) { if (t < o) sx[t] += sx[t + o]; __syncthreads(); }
    int x64 = (sx[0] == 0) ? 1 : 0;

    if (blockIdx.x == 0) {
        int cb = 0;
        for (int j = t; j < 4096; j += 256) if (bw[2 * j + 1]) cb++;
        sx[t] = cb;
        __syncthreads();
#pragma unroll
        for (int o = 128; o > 0; o >>= 1) { if (t < o) sx[t] += sx[t + o]; __syncthreads(); }
        if (t == 0) { g_b64 = (sx[0] == 0) ? 1 : 0; g_x64 = x64; }
    }

    int xv = load_small(xw, i, x64);
    g_Kc[i] = (unsigned int)(mix64(0x123456789ABCDEFULL +
                                   (unsigned long long)xv * 0x9E3779B97F4A7C15ULL) >> 16);
}

// ---------------- k1: heavy pass, warp-per-row + hidden scratch zeroing ----------------
__global__ __launch_bounds__(256) void k1_heavy(const float* __restrict__ adj) {
    int blk = blockIdx.x;
    int t = threadIdx.x;

    // hidden zeroing: counts (262144 int4 / 2048 blocks = 128/blk) + table (16 slots/blk)
    {
        int4* c4 = (int4*)g_counts;
        if (t < 128) c4[blk * 128 + t] = make_int4(0, 0, 0, 0);
        if (t >= 128 && t < 144) g_tab[blk * 16 + (t - 128)] = 0ULL;
    }

    int row  = blk * 8 + (t >> 5);
    int lane = t & 31;
    const uint4* __restrict__ arow = (const uint4*)(adj + (size_t)row * NN);
    const uint4* __restrict__ kt   = (const uint4*)g_Kc;

    unsigned long long a0 = 0, a1 = 0, a2 = 0, a3 = 0;
#pragma unroll 4
    for (int q = lane; q < 4096; q += 128) {
        uint4 u0 = __ldcs(arow + q);
        uint4 u1 = __ldcs(arow + q + 32);
        uint4 u2 = __ldcs(arow + q + 64);
        uint4 u3 = __ldcs(arow + q + 96);
        uint4 c0 = kt[q];
        uint4 c1 = kt[q + 32];
        uint4 c2 = kt[q + 64];
        uint4 c3 = kt[q + 96];
        a0 += (unsigned long long)u0.x * c0.x + (unsigned long long)u0.y * c0.y
            + (unsigned long long)u0.z * c0.z + (unsigned long long)u0.w * c0.w;
        a1 += (unsigned long long)u1.x * c1.x + (unsigned long long)u1.y * c1.y
            + (unsigned long long)u1.z * c1.z + (unsigned long long)u1.w * c1.w;
        a2 += (unsigned long long)u2.x * c2.x + (unsigned long long)u2.y * c2.y
            + (unsigned long long)u2.z * c2.z + (unsigned long long)u2.w * c2.w;
        a3 += (unsigned long long)u3.x * c3.x + (unsigned long long)u3.y * c3.y
            + (unsigned long long)u3.z * c3.z + (unsigned long long)u3.w * c3.w;
    }
    unsigned long long a = (a0 + a1) + (a2 + a3);
#pragma unroll
    for (int o = 16; o > 0; o >>= 1) a += __shfl_down_sync(0xffffffffu, a, o);
    if (lane == 0) g_acc[row] = a;
}

// ---------------- k_post: insert + lookup + rank + emit + norm (3 grid barriers) ----------------
__global__ __launch_bounds__(256) void k_post(const unsigned int* __restrict__ xw,
                                              const unsigned int* __restrict__ bw,
                                              const float* __restrict__ adj,
                                              float* __restrict__ out,
                                              long long out_size) {
    __shared__ int sScan[256];
    __shared__ int sOff[POSTB + 1];
    int t = threadIdx.x;
    int blk = blockIdx.x;
    int i = blk * 256 + t;                           // node id (POSTB*256 == NN)

    // ---- phase 1: key build + fused-slot hash insert (+lazy exact iso) ----
    unsigned long long acc = g_acc[i];
    bool iso = false;
    if (acc == 0ULL) {                               // w.p. ~2^-41 for non-isolated
        bool any = false;
        const float* rp = adj + (size_t)i * NN;
        for (int j = 0; j < NN && !any; j++) if (rp[j] != 0.0f) any = true;
        for (int r = 0; r < NN && !any; r++) if (adj[(size_t)r * NN + i] != 0.0f) any = true;
        iso = !any;
    }
    unsigned long long hk = 0ULL;                    // high-50-bit key, top bit set (never 0)
    if (!iso) {
        int xv = load_small(xw, i, g_x64);
        unsigned long long h = mix64(acc + (unsigned long long)xv * 0xA24BAED4963EE407ULL);
        hk = (h | 0x8000000000000000ULL) & 0xFFFFFFFFFFFFC000ULL;
        unsigned long long val = hk | (unsigned long long)i;
        unsigned int s = (unsigned int)(h >> 32) & (TS - 1);
        for (;;) {
            unsigned long long prev = atomicCAS(&g_tab[s], 0ULL, val);
            if (prev == 0ULL) break;
            if ((prev & 0xFFFFFFFFFFFFC000ULL) == hk) { atomicMin(&g_tab[s], val); break; }
            s = (s + 1) & (TS - 1);
        }
    }
    gridBarrier(1, POSTB);

    // ---- phase 2: lookup first-occurrence + block scan of is_first ----
    int f = -1;
    if (hk) {
        unsigned int s = (unsigned int)(hk >> 32) & (TS - 1);
        // recompute start slot from original h: hk>>32 differs from h>>32 in low masked bits;
        // use the same probe start as insert: derive from hk is unsafe, so recompute:
        // (we kept h's probe start = (h>>32)&(TS-1); note hk's bits 32..45 equal h's bits 32..45
        //  except bits 32..13? mask clears bits 0..13 only, so hk>>32 == h>>32. Safe.)
        for (;;) {
            unsigned long long v = g_tab[s];
            if ((v & 0xFFFFFFFFFFFFC000ULL) == hk) { f = (int)(v & 0x3FFFULL); break; }
            s = (s + 1) & (TS - 1);
        }
    }
    g_firsts[i] = f;
    int isf = (f == i) ? 1 : 0;
    sScan[t] = isf;
    __syncthreads();
#pragma unroll
    for (int o = 1; o < 256; o <<= 1) {
        int v = (t >= o) ? sScan[t - o] : 0;
        __syncthreads();
        sScan[t] += v;
        __syncthreads();
    }
    int incl = sScan[t];                             // inclusive in-block prefix
    g_rank[i] = incl;                                // partial rank (pre-barrier)
    if (t == 255) g_bsum[blk] = incl;
    gridBarrier(2, POSTB);

    // ---- phase 3+4: reconstruct global rank + emit colors + histogram ----
    if (t <= POSTB) sOff[t] = 0;
    __syncthreads();
    if (t == 0) {
        int run = 0;
#pragma unroll
        for (int b = 0; b < POSTB; b++) { sOff[b] = run; run += g_bsum[b]; }
    }
    __syncthreads();
    int c = (f < 0) ? 0 : (g_rank[f] + sOff[f >> 8]);
    if (c > 0) {
        int g = load_small(bw, i, g_b64) & (BB - 1);
        atomicAdd(&g_counts[g * NN + (c - 1)], 1);
    }
    long long histElems = (long long)BB * NN;
    long long colorBase = (out_size >= histElems) ? histElems : 0;
    long long oi = colorBase + i;
    if (oi < out_size) out[oi] = (float)c;
    gridBarrier(3, POSTB);                           // atomics visible before norm

    // ---- phase 5: per-graph L2 normalization (block blk <-> graph blk) ----
    {
        __shared__ double sred[256];
        const int4* cnt4 = (const int4*)(g_counts + blk * NN);
        double ss = 0.0;
#pragma unroll
        for (int j = t; j < NN / 4; j += 256) {
            int4 v = cnt4[j];
            ss += (double)v.x * v.x + (double)v.y * v.y
                + (double)v.z * v.z + (double)v.w * v.w;
        }
        sred[t] = ss; __syncthreads();
#pragma unroll
        for (int o = 128; o > 0; o >>= 1) { if (t < o) sred[t] += sred[t + o]; __syncthreads(); }
        double inv = 1.0 / sqrt(sred[0]);            // 0 -> inf -> NaN, matches reference
        if ((long long)(blk + 1) * NN <= out_size) {
            float4* o4 = (float4*)(out + (size_t)blk * NN);
            for (int j = t; j < NN / 4; j += 256) {
                int4 v = cnt4[j];
                float4 w;
                w.x = (float)((double)v.x * inv);
                w.y = (float)((double)v.y * inv);
                w.z = (float)((double)v.z * inv);
                w.w = (float)((double)v.w * inv);
                o4[j] = w;
            }
        }
    }
}

// ---------------- launcher ----------------
extern "C" void kernel_launch(void* const* d_in, const int* in_sizes, int n_in,
                              void* d_out, int out_size) {
    int iA = -1;
    for (int i = 0; i < n_in; i++)
        if ((long long)in_sizes[i] == (long long)NN * (long long)NN) iA = i;
    if (iA < 0) iA = (n_in > 1) ? 1 : 0;
    int ix = -1, ib = -1;
    for (int i = 0; i < n_in; i++) {
        if (i == iA) continue;
        if (ix < 0) ix = i; else if (ib < 0) ib = i;
    }
    if (ix < 0) ix = 0;
    if (ib < 0) ib = ix;

    const unsigned int* xw  = (const unsigned int*)d_in[ix];
    const float*        adj = (const float*)d_in[iA];
    const unsigned int* bw  = (const unsigned int*)d_in[ib];
    float* out = (float*)d_out;
    long long osz = (long long)out_size;

    k_pre<<<PREB, 256>>>(xw, bw);                    // #1
    k1_heavy<<<K1B, 256>>>(adj);                     // #2  (~170 us, DRAM-bound)
    k_post<<<POSTB, 256>>>(xw, bw, adj, out, osz);   // #3
}